// round 2
// baseline (speedup 1.0000x reference)
#include <cuda_runtime.h>

// Problem shape (fixed by the dataset)
#define BATCH 2
#define SEQ   2048
#define DIM   1024
#define NHEAD 16
#define DHEAD 64
#define MROWS (BATCH * SEQ)          // 4096
#define NQKV  (3 * DIM)              // 3072

// Scratch (allocation-free rule: __device__ globals)
__device__ float g_q[BATCH * NHEAD * SEQ * DHEAD];   // [b,h,s,dh], pre-scaled by 1/8
__device__ float g_k[BATCH * NHEAD * SEQ * DHEAD];
__device__ float g_v[BATCH * NHEAD * SEQ * DHEAD];
__device__ float g_att[BATCH * SEQ * DIM];           // merged-head attention output

// ---------------------------------------------------------------------------
// Kernel 1: QKV GEMM.  C[4096,3072] = X[4096,1024] @ W[1024,3072] + b
// Epilogue scatters into g_q/g_k/g_v in [b,h,s,dh] layout; q scaled by 0.125.
// 64x64 tile, BK=16, 256 threads, 4x4 per thread.
// ---------------------------------------------------------------------------
__global__ __launch_bounds__(256) void qkv_gemm_kernel(
    const float* __restrict__ X, const float* __restrict__ W,
    const float* __restrict__ bias)
{
    __shared__ float As[16][64];
    __shared__ float Bs[16][64];

    const int t  = threadIdx.x;
    const int m0 = blockIdx.y * 64;
    const int n0 = blockIdx.x * 64;
    const int tx = t & 15;
    const int ty = t >> 4;

    const int arow = t >> 2;           // 0..63
    const int acol = (t & 3) << 2;     // 0,4,8,12
    const int brow = t >> 4;           // 0..15
    const int bcol = (t & 15) << 2;    // 0..60

    const float* Aptr = X + (m0 + arow) * DIM + acol;
    const float* Bptr = W + brow * NQKV + n0 + bcol;

    float acc[4][4];
#pragma unroll
    for (int i = 0; i < 4; ++i)
#pragma unroll
        for (int j = 0; j < 4; ++j) acc[i][j] = 0.f;

    for (int kt = 0; kt < DIM / 16; ++kt) {
        float4 a = *(const float4*)(Aptr + kt * 16);
        float4 b = *(const float4*)(Bptr + (size_t)kt * 16 * NQKV);
        As[acol + 0][arow] = a.x;
        As[acol + 1][arow] = a.y;
        As[acol + 2][arow] = a.z;
        As[acol + 3][arow] = a.w;
        *(float4*)&Bs[brow][bcol] = b;
        __syncthreads();

#pragma unroll
        for (int k = 0; k < 16; ++k) {
            float4 av = *(const float4*)&As[k][ty << 2];
            float4 bv = *(const float4*)&Bs[k][tx << 2];
            acc[0][0] += av.x * bv.x; acc[0][1] += av.x * bv.y;
            acc[0][2] += av.x * bv.z; acc[0][3] += av.x * bv.w;
            acc[1][0] += av.y * bv.x; acc[1][1] += av.y * bv.y;
            acc[1][2] += av.y * bv.z; acc[1][3] += av.y * bv.w;
            acc[2][0] += av.z * bv.x; acc[2][1] += av.z * bv.y;
            acc[2][2] += av.z * bv.z; acc[2][3] += av.z * bv.w;
            acc[3][0] += av.w * bv.x; acc[3][1] += av.w * bv.y;
            acc[3][2] += av.w * bv.z; acc[3][3] += av.w * bv.w;
        }
        __syncthreads();
    }

#pragma unroll
    for (int i = 0; i < 4; ++i) {
        const int m = m0 + (ty << 2) + i;
        const int bb = m >> 11;          // batch
        const int s  = m & 2047;         // seq pos
#pragma unroll
        for (int j = 0; j < 4; ++j) {
            const int n = n0 + (tx << 2) + j;
            float v = acc[i][j] + bias[n];
            const int part = n >> 10;    // 0=q 1=k 2=v
            const int dd = n & 1023;
            const int h  = dd >> 6;
            const int hd = dd & 63;
            const int idx = (((bb << 4) + h) * SEQ + s) * DHEAD + hd;
            if (part == 0)      g_q[idx] = v * 0.125f;   // fold 1/sqrt(dh)
            else if (part == 1) g_k[idx] = v;
            else                g_v[idx] = v;
        }
    }
}

// ---------------------------------------------------------------------------
// Kernel 2: causal flash attention, fp32.
// One thread per query row; 64-row query tile per block (64 threads).
// K/V tiles (64x64) in SMEM (broadcast reads); score row staged in SMEM.
// Masked entries use exactly -10000.0f (matches GPT-2 additive mask).
// Output written merged-head into g_att[b, s, h*64+dh].
// ---------------------------------------------------------------------------
__global__ __launch_bounds__(64) void attn_kernel()
{
    __shared__ float4 Ks[64 * 16];       // 16 KB  [key][d4]
    __shared__ float4 Vs[64 * 16];       // 16 KB
    __shared__ float  Ssm[64][64];       // 16 KB  [key][thread]

    const int t    = threadIdx.x;        // 0..63  (query row within tile)
    const int qt   = blockIdx.x;         // query tile (0..31)
    const int bh   = blockIdx.y;         // b*16+h  (0..31)
    const int qrow = qt * 64 + t;

    const float*  Qb = g_q + (size_t)bh * SEQ * DHEAD;
    const float4* Kg = (const float4*)(g_k + (size_t)bh * SEQ * DHEAD);
    const float4* Vg = (const float4*)(g_v + (size_t)bh * SEQ * DHEAD);

    float4 q4[16];
    {
        const float4* qp = (const float4*)(Qb + qrow * DHEAD);
#pragma unroll
        for (int i = 0; i < 16; ++i) q4[i] = qp[i];
    }

    float  mrun = -1e30f, lrun = 0.f;
    float4 o4[16];
#pragma unroll
    for (int i = 0; i < 16; ++i) o4[i] = make_float4(0.f, 0.f, 0.f, 0.f);

    const int ntiles = qt + 1;           // causal: key tiles 0..qt
    for (int kt = 0; kt < ntiles; ++kt) {
        // cooperative load of K/V tile: 1024 float4 by 64 threads
#pragma unroll
        for (int i = 0; i < 16; ++i) {
            Ks[t + i * 64] = Kg[(size_t)kt * 1024 + t + i * 64];
            Vs[t + i * 64] = Vg[(size_t)kt * 1024 + t + i * 64];
        }
        __syncthreads();

        const int kbase = kt * 64;
        float tmax = -1e30f;

        // pass 1: scores (q already carries the 1/8 scale)
#pragma unroll 2
        for (int key = 0; key < 64; ++key) {
            const float4* kr = &Ks[key * 16];
            float acc = 0.f;
#pragma unroll
            for (int d = 0; d < 16; ++d) {
                float4 kv = kr[d];
                acc += q4[d].x * kv.x + q4[d].y * kv.y +
                       q4[d].z * kv.z + q4[d].w * kv.w;
            }
            if (kbase + key > qrow) acc = -10000.0f;
            Ssm[key][t] = acc;
            tmax = fmaxf(tmax, acc);
        }

        const float mnew = fmaxf(mrun, tmax);
        const float corr = __expf(mrun - mnew);
        lrun *= corr;
#pragma unroll
        for (int i = 0; i < 16; ++i) {
            o4[i].x *= corr; o4[i].y *= corr;
            o4[i].z *= corr; o4[i].w *= corr;
        }

        // pass 2: probabilities + PV accumulate
#pragma unroll 2
        for (int key = 0; key < 64; ++key) {
            const float p = __expf(Ssm[key][t] - mnew);
            lrun += p;
            const float4* vr = &Vs[key * 16];
#pragma unroll
            for (int d = 0; d < 16; ++d) {
                float4 vv = vr[d];
                o4[d].x += p * vv.x; o4[d].y += p * vv.y;
                o4[d].z += p * vv.z; o4[d].w += p * vv.w;
            }
        }
        mrun = mnew;
        __syncthreads();
    }

    const float inv = 1.f / lrun;
    const int b = bh >> 4;
    const int h = bh & 15;
    float4* dst = (float4*)(g_att + ((size_t)(b * SEQ + qrow)) * DIM + h * DHEAD);
#pragma unroll
    for (int i = 0; i < 16; ++i) {
        float4 v = o4[i];
        v.x *= inv; v.y *= inv; v.z *= inv; v.w *= inv;
        dst[i] = v;
    }
}

// ---------------------------------------------------------------------------
// Kernel 3: output projection. out[4096,1024] = g_att @ Wp[1024,1024] + bp
// ---------------------------------------------------------------------------
__global__ __launch_bounds__(256) void proj_gemm_kernel(
    const float* __restrict__ Wp, const float* __restrict__ bp,
    float* __restrict__ out)
{
    __shared__ float As[16][64];
    __shared__ float Bs[16][64];

    const int t  = threadIdx.x;
    const int m0 = blockIdx.y * 64;
    const int n0 = blockIdx.x * 64;
    const int tx = t & 15;
    const int ty = t >> 4;

    const int arow = t >> 2;
    const int acol = (t & 3) << 2;
    const int brow = t >> 4;
    const int bcol = (t & 15) << 2;

    const float* Aptr = g_att + (size_t)(m0 + arow) * DIM + acol;
    const float* Bptr = Wp + (size_t)brow * DIM + n0 + bcol;

    float acc[4][4];
#pragma unroll
    for (int i = 0; i < 4; ++i)
#pragma unroll
        for (int j = 0; j < 4; ++j) acc[i][j] = 0.f;

    for (int kt = 0; kt < DIM / 16; ++kt) {
        float4 a = *(const float4*)(Aptr + kt * 16);
        float4 b = *(const float4*)(Bptr + (size_t)kt * 16 * DIM);
        As[acol + 0][arow] = a.x;
        As[acol + 1][arow] = a.y;
        As[acol + 2][arow] = a.z;
        As[acol + 3][arow] = a.w;
        *(float4*)&Bs[brow][bcol] = b;
        __syncthreads();

#pragma unroll
        for (int k = 0; k < 16; ++k) {
            float4 av = *(const float4*)&As[k][ty << 2];
            float4 bv = *(const float4*)&Bs[k][tx << 2];
            acc[0][0] += av.x * bv.x; acc[0][1] += av.x * bv.y;
            acc[0][2] += av.x * bv.z; acc[0][3] += av.x * bv.w;
            acc[1][0] += av.y * bv.x; acc[1][1] += av.y * bv.y;
            acc[1][2] += av.y * bv.z; acc[1][3] += av.y * bv.w;
            acc[2][0] += av.z * bv.x; acc[2][1] += av.z * bv.y;
            acc[2][2] += av.z * bv.z; acc[2][3] += av.z * bv.w;
            acc[3][0] += av.w * bv.x; acc[3][1] += av.w * bv.y;
            acc[3][2] += av.w * bv.z; acc[3][3] += av.w * bv.w;
        }
        __syncthreads();
    }

#pragma unroll
    for (int i = 0; i < 4; ++i) {
        const int m = m0 + (ty << 2) + i;
#pragma unroll
        for (int j = 0; j < 4; ++j) {
            const int n = n0 + (tx << 2) + j;
            out[(size_t)m * DIM + n] = acc[i][j] + bp[n];
        }
    }
}

// ---------------------------------------------------------------------------
extern "C" void kernel_launch(void* const* d_in, const int* in_sizes, int n_in,
                              void* d_out, int out_size)
{
    const float* x      = (const float*)d_in[0];
    const float* w_attn = (const float*)d_in[1];
    const float* b_attn = (const float*)d_in[2];
    const float* w_proj = (const float*)d_in[3];
    const float* b_proj = (const float*)d_in[4];
    float* out = (float*)d_out;

    // 1) QKV GEMM + scatter to [b,h,s,dh]
    qkv_gemm_kernel<<<dim3(NQKV / 64, MROWS / 64), 256>>>(x, w_attn, b_attn);
    // 2) causal flash attention
    attn_kernel<<<dim3(SEQ / 64, BATCH * NHEAD), 64>>>();
    // 3) output projection
    proj_gemm_kernel<<<dim3(DIM / 64, MROWS / 64), 256>>>(w_proj, b_proj, out);
}

// round 4
// speedup vs baseline: 1.5115x; 1.5115x over previous
#include <cuda_runtime.h>
#include <cuda_bf16.h>
#include <cstdint>

// Problem shape (fixed by the dataset)
#define BATCH 2
#define SEQ   2048
#define DIM   1024
#define NHEAD 16
#define DHEAD 64
#define MROWS (BATCH * SEQ)          // 4096
#define NQKV  (3 * DIM)              // 3072
#define KTOT  1024

// ---------------------------------------------------------------------------
// Scratch (allocation-free rule: __device__ globals)
// ---------------------------------------------------------------------------
__device__ float g_q[BATCH * NHEAD * SEQ * DHEAD];   // [b,h,s,dh], q pre-scaled 1/8
__device__ float g_k[BATCH * NHEAD * SEQ * DHEAD];
__device__ float g_v[BATCH * NHEAD * SEQ * DHEAD];
__device__ float g_att[BATCH * SEQ * DIM];

// bf16 split scratch (A buffers reused for x and g_att)
__device__ __nv_bfloat16 s_a_hi[MROWS * KTOT];
__device__ __nv_bfloat16 s_a_lo[MROWS * KTOT];
__device__ __nv_bfloat16 s_wq_hi[NQKV * KTOT];       // w_attn^T  [3072,1024]
__device__ __nv_bfloat16 s_wq_lo[NQKV * KTOT];
__device__ __nv_bfloat16 s_wp_hi[DIM * KTOT];        // w_proj^T  [1024,1024]
__device__ __nv_bfloat16 s_wp_lo[DIM * KTOT];

// ---------------------------------------------------------------------------
// PTX helpers: ldmatrix + legacy mma.sync (baseline ISA — compiles for sm_103)
// ---------------------------------------------------------------------------
__device__ __forceinline__ uint32_t smem_u32(const void* p) {
    uint32_t a;
    asm("{ .reg .u64 t; cvta.to.shared.u64 t, %1; cvt.u32.u64 %0, t; }"
        : "=r"(a) : "l"(p));
    return a;
}
__device__ __forceinline__ void ldsm4(uint32_t addr, uint32_t& r0, uint32_t& r1,
                                      uint32_t& r2, uint32_t& r3) {
    asm volatile("ldmatrix.sync.aligned.m8n8.x4.shared.b16 {%0,%1,%2,%3}, [%4];"
                 : "=r"(r0), "=r"(r1), "=r"(r2), "=r"(r3) : "r"(addr));
}
__device__ __forceinline__ void mma_bf16(float& c0, float& c1, float& c2, float& c3,
                                         uint32_t a0, uint32_t a1, uint32_t a2, uint32_t a3,
                                         uint32_t b0, uint32_t b1) {
    asm volatile("mma.sync.aligned.m16n8k16.row.col.f32.bf16.bf16.f32 "
                 "{%0,%1,%2,%3}, {%4,%5,%6,%7}, {%8,%9}, {%0,%1,%2,%3};"
                 : "+f"(c0), "+f"(c1), "+f"(c2), "+f"(c3)
                 : "r"(a0), "r"(a1), "r"(a2), "r"(a3), "r"(b0), "r"(b1));
}

// ---------------------------------------------------------------------------
// Prep kernel 1: fp32 row-major -> bf16 hi/lo split (same layout)
// ---------------------------------------------------------------------------
__global__ __launch_bounds__(256) void split_kernel(
    const float* __restrict__ src, __nv_bfloat16* __restrict__ hi,
    __nv_bfloat16* __restrict__ lo, int n4)
{
    int i = blockIdx.x * 256 + threadIdx.x;
    if (i >= n4) return;
    float4 v = ((const float4*)src)[i];
    __nv_bfloat16 h0 = __float2bfloat16_rn(v.x);
    __nv_bfloat16 h1 = __float2bfloat16_rn(v.y);
    __nv_bfloat16 h2 = __float2bfloat16_rn(v.z);
    __nv_bfloat16 h3 = __float2bfloat16_rn(v.w);
    __nv_bfloat16 l0 = __float2bfloat16_rn(v.x - __bfloat162float(h0));
    __nv_bfloat16 l1 = __float2bfloat16_rn(v.y - __bfloat162float(h1));
    __nv_bfloat16 l2 = __float2bfloat16_rn(v.z - __bfloat162float(h2));
    __nv_bfloat16 l3 = __float2bfloat16_rn(v.w - __bfloat162float(h3));
    uint2 uh, ul;
    uh.x = (uint32_t)__bfloat16_as_ushort(h0) | ((uint32_t)__bfloat16_as_ushort(h1) << 16);
    uh.y = (uint32_t)__bfloat16_as_ushort(h2) | ((uint32_t)__bfloat16_as_ushort(h3) << 16);
    ul.x = (uint32_t)__bfloat16_as_ushort(l0) | ((uint32_t)__bfloat16_as_ushort(l1) << 16);
    ul.y = (uint32_t)__bfloat16_as_ushort(l2) | ((uint32_t)__bfloat16_as_ushort(l3) << 16);
    *(uint2*)(hi + (size_t)i * 4) = uh;
    *(uint2*)(lo + (size_t)i * 4) = ul;
}

// ---------------------------------------------------------------------------
// Prep kernel 2: w[K,N] fp32 -> wT hi/lo bf16 [N,K]
// ---------------------------------------------------------------------------
__global__ __launch_bounds__(256) void transp_split_kernel(
    const float* __restrict__ w, int K, int N,
    __nv_bfloat16* __restrict__ out_hi, __nv_bfloat16* __restrict__ out_lo)
{
    __shared__ float t[32][33];
    const int tx = threadIdx.x, ty = threadIdx.y;
    const int n0 = blockIdx.x * 32, k0 = blockIdx.y * 32;
#pragma unroll
    for (int i = 0; i < 4; ++i)
        t[ty + i * 8][tx] = w[(size_t)(k0 + ty + i * 8) * N + n0 + tx];
    __syncthreads();
#pragma unroll
    for (int i = 0; i < 4; ++i) {
        const int n = n0 + ty + i * 8;
        float v = t[tx][ty + i * 8];
        __nv_bfloat16 h = __float2bfloat16_rn(v);
        __nv_bfloat16 l = __float2bfloat16_rn(v - __bfloat162float(h));
        out_hi[(size_t)n * K + k0 + tx] = h;
        out_lo[(size_t)n * K + k0 + tx] = l;
    }
}

// ---------------------------------------------------------------------------
// HMMA GEMM:  D[M,N] = A[M,K] @ B^T[N,K] + bias  (bf16 split-2, fp32 accum)
// CTA 128x128, BK=32, 8 warps (2x4), warp tile 64x32 (4x4 of m16n8k16).
// mode 0: QKV scatter epilogue (q*0.125); mode 1: plain output.
// ---------------------------------------------------------------------------
#define BM 128
#define BN 128
#define BK 32
#define ROWB 80   // 64B data + 16B pad per smem row (conflict-free ldmatrix)

__global__ __launch_bounds__(256) void tc_gemm_kernel(
    const __nv_bfloat16* __restrict__ Ahi, const __nv_bfloat16* __restrict__ Alo,
    const __nv_bfloat16* __restrict__ Bhi, const __nv_bfloat16* __restrict__ Blo,
    const float* __restrict__ bias, float* __restrict__ outp, int mode)
{
    __shared__ __align__(16) char smA_hi[BM * ROWB];
    __shared__ __align__(16) char smA_lo[BM * ROWB];
    __shared__ __align__(16) char smB_hi[BN * ROWB];
    __shared__ __align__(16) char smB_lo[BN * ROWB];

    const int tid  = threadIdx.x;
    const int w    = tid >> 5;
    const int lane = tid & 31;
    const int m0 = blockIdx.y * BM;
    const int n0 = blockIdx.x * BN;
    const int wm = (w >> 2) * 64;      // warp M offset
    const int wn = (w & 3) * 32;       // warp N offset

    // global staging: thread covers rows (srow, srow+64), one 16B seg each
    const int srow = tid >> 2;         // 0..63
    const int sseg = tid & 3;          // 16B segment of the 64B row
    const size_t gA = (size_t)(m0 + srow) * KTOT + sseg * 8;
    const size_t gB = (size_t)(n0 + srow) * KTOT + sseg * 8;
    const size_t rstep = (size_t)64 * KTOT;

    const uint32_t sAhi = smem_u32(smA_hi), sAlo = smem_u32(smA_lo);
    const uint32_t sBhi = smem_u32(smB_hi), sBlo = smem_u32(smB_lo);
    const uint32_t soff0 = (uint32_t)(srow * ROWB + sseg * 16);
    const uint32_t soff1 = soff0 + 64 * ROWB;

    float acc[4][4][4];
#pragma unroll
    for (int i = 0; i < 4; ++i)
#pragma unroll
        for (int j = 0; j < 4; ++j)
#pragma unroll
            for (int e = 0; e < 4; ++e) acc[i][j][e] = 0.f;

    uint4 st[8];
    // prologue: stage kt=0
    {
        st[0] = *(const uint4*)(Ahi + gA);          st[1] = *(const uint4*)(Ahi + gA + rstep);
        st[2] = *(const uint4*)(Alo + gA);          st[3] = *(const uint4*)(Alo + gA + rstep);
        st[4] = *(const uint4*)(Bhi + gB);          st[5] = *(const uint4*)(Bhi + gB + rstep);
        st[6] = *(const uint4*)(Blo + gB);          st[7] = *(const uint4*)(Blo + gB + rstep);
    }

    // fragment address precompute
    const int ar = lane & 15, ah = lane >> 4;
    const uint32_t aoffb = (uint32_t)((wm + ar) * ROWB + ah * 16);
    const int grp = lane >> 3, l8 = lane & 7;
    const uint32_t boffb = (uint32_t)((wn + ((grp >> 1) << 3) + l8) * ROWB + (grp & 1) * 16);

    for (int kt = 0; kt < KTOT / BK; ++kt) {
        __syncthreads();   // previous compute done before smem overwrite
        *(uint4*)(smA_hi + soff0) = st[0];  *(uint4*)(smA_hi + soff1) = st[1];
        *(uint4*)(smA_lo + soff0) = st[2];  *(uint4*)(smA_lo + soff1) = st[3];
        *(uint4*)(smB_hi + soff0) = st[4];  *(uint4*)(smB_hi + soff1) = st[5];
        *(uint4*)(smB_lo + soff0) = st[6];  *(uint4*)(smB_lo + soff1) = st[7];
        __syncthreads();

        if (kt + 1 < KTOT / BK) {
            const size_t ka = gA + (size_t)(kt + 1) * BK;
            const size_t kb = gB + (size_t)(kt + 1) * BK;
            st[0] = *(const uint4*)(Ahi + ka);      st[1] = *(const uint4*)(Ahi + ka + rstep);
            st[2] = *(const uint4*)(Alo + ka);      st[3] = *(const uint4*)(Alo + ka + rstep);
            st[4] = *(const uint4*)(Bhi + kb);      st[5] = *(const uint4*)(Bhi + kb + rstep);
            st[6] = *(const uint4*)(Blo + kb);      st[7] = *(const uint4*)(Blo + kb + rstep);
        }

#pragma unroll
        for (int ks = 0; ks < 2; ++ks) {
            const uint32_t akoff = aoffb + ks * 32;
            const uint32_t bkoff = boffb + ks * 32;

            uint32_t fah[4][4], fal[4][4];
#pragma unroll
            for (int mt = 0; mt < 4; ++mt) {
                ldsm4(sAhi + akoff + mt * 16 * ROWB,
                      fah[mt][0], fah[mt][1], fah[mt][2], fah[mt][3]);
                ldsm4(sAlo + akoff + mt * 16 * ROWB,
                      fal[mt][0], fal[mt][1], fal[mt][2], fal[mt][3]);
            }
            uint32_t fbh[8], fbl[8];
            ldsm4(sBhi + bkoff,             fbh[0], fbh[1], fbh[2], fbh[3]);
            ldsm4(sBhi + bkoff + 16 * ROWB, fbh[4], fbh[5], fbh[6], fbh[7]);
            ldsm4(sBlo + bkoff,             fbl[0], fbl[1], fbl[2], fbl[3]);
            ldsm4(sBlo + bkoff + 16 * ROWB, fbl[4], fbl[5], fbl[6], fbl[7]);

#pragma unroll
            for (int mt = 0; mt < 4; ++mt) {
#pragma unroll
                for (int nt = 0; nt < 4; ++nt) {
                    float* c = acc[mt][nt];
                    mma_bf16(c[0], c[1], c[2], c[3],
                             fah[mt][0], fah[mt][1], fah[mt][2], fah[mt][3],
                             fbh[nt * 2], fbh[nt * 2 + 1]);
                    mma_bf16(c[0], c[1], c[2], c[3],
                             fah[mt][0], fah[mt][1], fah[mt][2], fah[mt][3],
                             fbl[nt * 2], fbl[nt * 2 + 1]);
                    mma_bf16(c[0], c[1], c[2], c[3],
                             fal[mt][0], fal[mt][1], fal[mt][2], fal[mt][3],
                             fbh[nt * 2], fbh[nt * 2 + 1]);
                }
            }
        }
    }

    // ------------------------- epilogue -------------------------
    const int erow = (lane >> 2);
    const int ecol = (lane & 3) * 2;
#pragma unroll
    for (int mt = 0; mt < 4; ++mt) {
#pragma unroll
        for (int nt = 0; nt < 4; ++nt) {
#pragma unroll
            for (int half = 0; half < 2; ++half) {
                const int row = m0 + wm + mt * 16 + erow + half * 8;
                const int col = n0 + wn + nt * 8 + ecol;
                float v0 = acc[mt][nt][half * 2 + 0] + bias[col];
                float v1 = acc[mt][nt][half * 2 + 1] + bias[col + 1];
                if (mode == 0) {
                    const int bb = row >> 11, s = row & 2047;
                    const int part = col >> 10;
                    const int dd = col & 1023;
                    const int h = dd >> 6, hd = dd & 63;
                    if (part == 0) { v0 *= 0.125f; v1 *= 0.125f; }
                    float* dst = (part == 0 ? g_q : (part == 1 ? g_k : g_v)) +
                                 ((size_t)((bb << 4) + h) * SEQ + s) * DHEAD + hd;
                    *(float2*)dst = make_float2(v0, v1);
                } else {
                    *(float2*)(outp + (size_t)row * DIM + col) = make_float2(v0, v1);
                }
            }
        }
    }
}

// ---------------------------------------------------------------------------
// Causal flash attention, fp32 (unchanged — known correct).
// ---------------------------------------------------------------------------
__global__ __launch_bounds__(64) void attn_kernel()
{
    __shared__ float4 Ks[64 * 16];
    __shared__ float4 Vs[64 * 16];
    __shared__ float  Ssm[64][64];

    const int t    = threadIdx.x;
    const int qt   = blockIdx.x;
    const int bh   = blockIdx.y;
    const int qrow = qt * 64 + t;

    const float*  Qb = g_q + (size_t)bh * SEQ * DHEAD;
    const float4* Kg = (const float4*)(g_k + (size_t)bh * SEQ * DHEAD);
    const float4* Vg = (const float4*)(g_v + (size_t)bh * SEQ * DHEAD);

    float4 q4[16];
    {
        const float4* qp = (const float4*)(Qb + qrow * DHEAD);
#pragma unroll
        for (int i = 0; i < 16; ++i) q4[i] = qp[i];
    }

    float  mrun = -1e30f, lrun = 0.f;
    float4 o4[16];
#pragma unroll
    for (int i = 0; i < 16; ++i) o4[i] = make_float4(0.f, 0.f, 0.f, 0.f);

    const int ntiles = qt + 1;
    for (int kt = 0; kt < ntiles; ++kt) {
#pragma unroll
        for (int i = 0; i < 16; ++i) {
            Ks[t + i * 64] = Kg[(size_t)kt * 1024 + t + i * 64];
            Vs[t + i * 64] = Vg[(size_t)kt * 1024 + t + i * 64];
        }
        __syncthreads();

        const int kbase = kt * 64;
        float tmax = -1e30f;

#pragma unroll 2
        for (int key = 0; key < 64; ++key) {
            const float4* kr = &Ks[key * 16];
            float acc = 0.f;
#pragma unroll
            for (int d = 0; d < 16; ++d) {
                float4 kv = kr[d];
                acc += q4[d].x * kv.x + q4[d].y * kv.y +
                       q4[d].z * kv.z + q4[d].w * kv.w;
            }
            if (kbase + key > qrow) acc = -10000.0f;
            Ssm[key][t] = acc;
            tmax = fmaxf(tmax, acc);
        }

        const float mnew = fmaxf(mrun, tmax);
        const float corr = __expf(mrun - mnew);
        lrun *= corr;
#pragma unroll
        for (int i = 0; i < 16; ++i) {
            o4[i].x *= corr; o4[i].y *= corr;
            o4[i].z *= corr; o4[i].w *= corr;
        }

#pragma unroll 2
        for (int key = 0; key < 64; ++key) {
            const float p = __expf(Ssm[key][t] - mnew);
            lrun += p;
            const float4* vr = &Vs[key * 16];
#pragma unroll
            for (int d = 0; d < 16; ++d) {
                float4 vv = vr[d];
                o4[d].x += p * vv.x; o4[d].y += p * vv.y;
                o4[d].z += p * vv.z; o4[d].w += p * vv.w;
            }
        }
        mrun = mnew;
        __syncthreads();
    }

    const float inv = 1.f / lrun;
    const int b = bh >> 4;
    const int h = bh & 15;
    float4* dst = (float4*)(g_att + ((size_t)(b * SEQ + qrow)) * DIM + h * DHEAD);
#pragma unroll
    for (int i = 0; i < 16; ++i) {
        float4 v = o4[i];
        v.x *= inv; v.y *= inv; v.z *= inv; v.w *= inv;
        dst[i] = v;
    }
}

// ---------------------------------------------------------------------------
extern "C" void kernel_launch(void* const* d_in, const int* in_sizes, int n_in,
                              void* d_out, int out_size)
{
    const float* x      = (const float*)d_in[0];
    const float* w_attn = (const float*)d_in[1];
    const float* b_attn = (const float*)d_in[2];
    const float* w_proj = (const float*)d_in[3];
    const float* b_proj = (const float*)d_in[4];
    float* out = (float*)d_out;

    __nv_bfloat16 *xa_hi, *xa_lo, *wq_hi, *wq_lo, *wp_hi, *wp_lo;
    cudaGetSymbolAddress((void**)&xa_hi, s_a_hi);
    cudaGetSymbolAddress((void**)&xa_lo, s_a_lo);
    cudaGetSymbolAddress((void**)&wq_hi, s_wq_hi);
    cudaGetSymbolAddress((void**)&wq_lo, s_wq_lo);
    cudaGetSymbolAddress((void**)&wp_hi, s_wp_hi);
    cudaGetSymbolAddress((void**)&wp_lo, s_wp_lo);
    float* att_ptr;
    cudaGetSymbolAddress((void**)&att_ptr, g_att);

    // 1) split x -> bf16 hi/lo
    split_kernel<<<(MROWS * KTOT / 4 + 255) / 256, 256>>>(x, xa_hi, xa_lo, MROWS * KTOT / 4);
    // 2) transpose+split weights
    transp_split_kernel<<<dim3(NQKV / 32, KTOT / 32), dim3(32, 8)>>>(w_attn, KTOT, NQKV, wq_hi, wq_lo);
    transp_split_kernel<<<dim3(DIM / 32, KTOT / 32), dim3(32, 8)>>>(w_proj, KTOT, DIM, wp_hi, wp_lo);
    // 3) QKV GEMM on tensor cores (scatter epilogue)
    tc_gemm_kernel<<<dim3(NQKV / BN, MROWS / BM), 256>>>(
        xa_hi, xa_lo, wq_hi, wq_lo, b_attn, nullptr, 0);
    // 4) causal flash attention
    attn_kernel<<<dim3(SEQ / 64, BATCH * NHEAD), 64>>>();
    // 5) split g_att -> bf16 hi/lo (reuse x buffers)
    split_kernel<<<(MROWS * KTOT / 4 + 255) / 256, 256>>>(att_ptr, xa_hi, xa_lo, MROWS * KTOT / 4);
    // 6) output projection on tensor cores
    tc_gemm_kernel<<<dim3(DIM / BN, MROWS / BM), 256>>>(
        xa_hi, xa_lo, wp_hi, wp_lo, b_proj, out, 1);
}

// round 5
// speedup vs baseline: 3.2456x; 2.1473x over previous
#include <cuda_runtime.h>
#include <cuda_bf16.h>
#include <cstdint>

// Problem shape (fixed by the dataset)
#define BATCH 2
#define SEQ   2048
#define DIM   1024
#define NHEAD 16
#define DHEAD 64
#define MROWS (BATCH * SEQ)          // 4096
#define NQKV  (3 * DIM)              // 3072
#define KTOT  1024

// ---------------------------------------------------------------------------
// Scratch (allocation-free rule: __device__ globals), all bf16 split-2 pairs
// ---------------------------------------------------------------------------
__device__ __nv_bfloat16 s_a_hi[MROWS * KTOT];   // GEMM A: x, then attention out
__device__ __nv_bfloat16 s_a_lo[MROWS * KTOT];
__device__ __nv_bfloat16 s_wq_hi[NQKV * KTOT];   // w_attn^T [3072,1024]
__device__ __nv_bfloat16 s_wq_lo[NQKV * KTOT];
__device__ __nv_bfloat16 s_wp_hi[DIM * KTOT];    // w_proj^T [1024,1024]
__device__ __nv_bfloat16 s_wp_lo[DIM * KTOT];
// attention operands, written by QKV epilogue
__device__ __nv_bfloat16 s_q_hi[BATCH * NHEAD * SEQ * DHEAD];  // [bh,s,dh], q*0.125
__device__ __nv_bfloat16 s_q_lo[BATCH * NHEAD * SEQ * DHEAD];
__device__ __nv_bfloat16 s_k_hi[BATCH * NHEAD * SEQ * DHEAD];  // [bh,s,dh]
__device__ __nv_bfloat16 s_k_lo[BATCH * NHEAD * SEQ * DHEAD];
__device__ __nv_bfloat16 s_vt_hi[BATCH * NHEAD * DHEAD * SEQ]; // [bh,dh,s]
__device__ __nv_bfloat16 s_vt_lo[BATCH * NHEAD * DHEAD * SEQ];

// ---------------------------------------------------------------------------
// PTX helpers (baseline ISA — compiles for sm_103)
// ---------------------------------------------------------------------------
__device__ __forceinline__ uint32_t smem_u32(const void* p) {
    uint32_t a;
    asm("{ .reg .u64 t; cvta.to.shared.u64 t, %1; cvt.u32.u64 %0, t; }"
        : "=r"(a) : "l"(p));
    return a;
}
__device__ __forceinline__ void ldsm4(uint32_t addr, uint32_t& r0, uint32_t& r1,
                                      uint32_t& r2, uint32_t& r3) {
    asm volatile("ldmatrix.sync.aligned.m8n8.x4.shared.b16 {%0,%1,%2,%3}, [%4];"
                 : "=r"(r0), "=r"(r1), "=r"(r2), "=r"(r3) : "r"(addr));
}
__device__ __forceinline__ void mma_bf16(float& c0, float& c1, float& c2, float& c3,
                                         uint32_t a0, uint32_t a1, uint32_t a2, uint32_t a3,
                                         uint32_t b0, uint32_t b1) {
    asm volatile("mma.sync.aligned.m16n8k16.row.col.f32.bf16.bf16.f32 "
                 "{%0,%1,%2,%3}, {%4,%5,%6,%7}, {%8,%9}, {%0,%1,%2,%3};"
                 : "+f"(c0), "+f"(c1), "+f"(c2), "+f"(c3)
                 : "r"(a0), "r"(a1), "r"(a2), "r"(a3), "r"(b0), "r"(b1));
}
__device__ __forceinline__ void split2(float v, __nv_bfloat16& h, __nv_bfloat16& l) {
    h = __float2bfloat16_rn(v);
    l = __float2bfloat16_rn(v - __bfloat162float(h));
}
__device__ __forceinline__ uint32_t packbf(__nv_bfloat16 a, __nv_bfloat16 b) {
    return (uint32_t)__bfloat16_as_ushort(a) | ((uint32_t)__bfloat16_as_ushort(b) << 16);
}

// ---------------------------------------------------------------------------
// Prep kernels
// ---------------------------------------------------------------------------
__global__ __launch_bounds__(256) void split_kernel(
    const float* __restrict__ src, __nv_bfloat16* __restrict__ hi,
    __nv_bfloat16* __restrict__ lo, int n4)
{
    int i = blockIdx.x * 256 + threadIdx.x;
    if (i >= n4) return;
    float4 v = ((const float4*)src)[i];
    __nv_bfloat16 h0, l0, h1, l1, h2, l2, h3, l3;
    split2(v.x, h0, l0); split2(v.y, h1, l1);
    split2(v.z, h2, l2); split2(v.w, h3, l3);
    uint2 uh = make_uint2(packbf(h0, h1), packbf(h2, h3));
    uint2 ul = make_uint2(packbf(l0, l1), packbf(l2, l3));
    *(uint2*)(hi + (size_t)i * 4) = uh;
    *(uint2*)(lo + (size_t)i * 4) = ul;
}

__global__ __launch_bounds__(256) void transp_split_kernel(
    const float* __restrict__ w, int K, int N,
    __nv_bfloat16* __restrict__ out_hi, __nv_bfloat16* __restrict__ out_lo)
{
    __shared__ float t[32][33];
    const int tx = threadIdx.x, ty = threadIdx.y;
    const int n0 = blockIdx.x * 32, k0 = blockIdx.y * 32;
#pragma unroll
    for (int i = 0; i < 4; ++i)
        t[ty + i * 8][tx] = w[(size_t)(k0 + ty + i * 8) * N + n0 + tx];
    __syncthreads();
#pragma unroll
    for (int i = 0; i < 4; ++i) {
        const int n = n0 + ty + i * 8;
        float v = t[tx][ty + i * 8];
        __nv_bfloat16 h, l;
        split2(v, h, l);
        out_hi[(size_t)n * K + k0 + tx] = h;
        out_lo[(size_t)n * K + k0 + tx] = l;
    }
}

// ---------------------------------------------------------------------------
// HMMA GEMM (validated in R4): D[M,N] = A @ B^T + bias, bf16 split-2.
// mode 0: QKV epilogue -> bf16 split q/k (k-major) and vt (transposed)
// mode 1: plain fp32 out
// ---------------------------------------------------------------------------
#define BM 128
#define BN 128
#define BK 32
#define ROWB 80

__global__ __launch_bounds__(256) void tc_gemm_kernel(
    const __nv_bfloat16* __restrict__ Ahi, const __nv_bfloat16* __restrict__ Alo,
    const __nv_bfloat16* __restrict__ Bhi, const __nv_bfloat16* __restrict__ Blo,
    const float* __restrict__ bias, float* __restrict__ outp, int mode)
{
    __shared__ __align__(16) char smA_hi[BM * ROWB];
    __shared__ __align__(16) char smA_lo[BM * ROWB];
    __shared__ __align__(16) char smB_hi[BN * ROWB];
    __shared__ __align__(16) char smB_lo[BN * ROWB];

    const int tid  = threadIdx.x;
    const int w    = tid >> 5;
    const int lane = tid & 31;
    const int m0 = blockIdx.y * BM;
    const int n0 = blockIdx.x * BN;
    const int wm = (w >> 2) * 64;
    const int wn = (w & 3) * 32;

    const int srow = tid >> 2;
    const int sseg = tid & 3;
    const size_t gA = (size_t)(m0 + srow) * KTOT + sseg * 8;
    const size_t gB = (size_t)(n0 + srow) * KTOT + sseg * 8;
    const size_t rstep = (size_t)64 * KTOT;

    const uint32_t sAhi = smem_u32(smA_hi), sAlo = smem_u32(smA_lo);
    const uint32_t sBhi = smem_u32(smB_hi), sBlo = smem_u32(smB_lo);
    const uint32_t soff0 = (uint32_t)(srow * ROWB + sseg * 16);
    const uint32_t soff1 = soff0 + 64 * ROWB;

    float acc[4][4][4];
#pragma unroll
    for (int i = 0; i < 4; ++i)
#pragma unroll
        for (int j = 0; j < 4; ++j)
#pragma unroll
            for (int e = 0; e < 4; ++e) acc[i][j][e] = 0.f;

    uint4 st[8];
    st[0] = *(const uint4*)(Ahi + gA);          st[1] = *(const uint4*)(Ahi + gA + rstep);
    st[2] = *(const uint4*)(Alo + gA);          st[3] = *(const uint4*)(Alo + gA + rstep);
    st[4] = *(const uint4*)(Bhi + gB);          st[5] = *(const uint4*)(Bhi + gB + rstep);
    st[6] = *(const uint4*)(Blo + gB);          st[7] = *(const uint4*)(Blo + gB + rstep);

    const int ar = lane & 15, ah = lane >> 4;
    const uint32_t aoffb = (uint32_t)((wm + ar) * ROWB + ah * 16);
    const int grp = lane >> 3, l8 = lane & 7;
    const uint32_t boffb = (uint32_t)((wn + ((grp >> 1) << 3) + l8) * ROWB + (grp & 1) * 16);

    for (int kt = 0; kt < KTOT / BK; ++kt) {
        __syncthreads();
        *(uint4*)(smA_hi + soff0) = st[0];  *(uint4*)(smA_hi + soff1) = st[1];
        *(uint4*)(smA_lo + soff0) = st[2];  *(uint4*)(smA_lo + soff1) = st[3];
        *(uint4*)(smB_hi + soff0) = st[4];  *(uint4*)(smB_hi + soff1) = st[5];
        *(uint4*)(smB_lo + soff0) = st[6];  *(uint4*)(smB_lo + soff1) = st[7];
        __syncthreads();

        if (kt + 1 < KTOT / BK) {
            const size_t ka = gA + (size_t)(kt + 1) * BK;
            const size_t kb = gB + (size_t)(kt + 1) * BK;
            st[0] = *(const uint4*)(Ahi + ka);      st[1] = *(const uint4*)(Ahi + ka + rstep);
            st[2] = *(const uint4*)(Alo + ka);      st[3] = *(const uint4*)(Alo + ka + rstep);
            st[4] = *(const uint4*)(Bhi + kb);      st[5] = *(const uint4*)(Bhi + kb + rstep);
            st[6] = *(const uint4*)(Blo + kb);      st[7] = *(const uint4*)(Blo + kb + rstep);
        }

#pragma unroll
        for (int ks = 0; ks < 2; ++ks) {
            const uint32_t akoff = aoffb + ks * 32;
            const uint32_t bkoff = boffb + ks * 32;

            uint32_t fah[4][4], fal[4][4];
#pragma unroll
            for (int mt = 0; mt < 4; ++mt) {
                ldsm4(sAhi + akoff + mt * 16 * ROWB,
                      fah[mt][0], fah[mt][1], fah[mt][2], fah[mt][3]);
                ldsm4(sAlo + akoff + mt * 16 * ROWB,
                      fal[mt][0], fal[mt][1], fal[mt][2], fal[mt][3]);
            }
            uint32_t fbh[8], fbl[8];
            ldsm4(sBhi + bkoff,             fbh[0], fbh[1], fbh[2], fbh[3]);
            ldsm4(sBhi + bkoff + 16 * ROWB, fbh[4], fbh[5], fbh[6], fbh[7]);
            ldsm4(sBlo + bkoff,             fbl[0], fbl[1], fbl[2], fbl[3]);
            ldsm4(sBlo + bkoff + 16 * ROWB, fbl[4], fbl[5], fbl[6], fbl[7]);

#pragma unroll
            for (int mt = 0; mt < 4; ++mt) {
#pragma unroll
                for (int nt = 0; nt < 4; ++nt) {
                    float* c = acc[mt][nt];
                    mma_bf16(c[0], c[1], c[2], c[3],
                             fah[mt][0], fah[mt][1], fah[mt][2], fah[mt][3],
                             fbh[nt * 2], fbh[nt * 2 + 1]);
                    mma_bf16(c[0], c[1], c[2], c[3],
                             fah[mt][0], fah[mt][1], fah[mt][2], fah[mt][3],
                             fbl[nt * 2], fbl[nt * 2 + 1]);
                    mma_bf16(c[0], c[1], c[2], c[3],
                             fal[mt][0], fal[mt][1], fal[mt][2], fal[mt][3],
                             fbh[nt * 2], fbh[nt * 2 + 1]);
                }
            }
        }
    }

    // epilogue
    const int erow = (lane >> 2);
    const int ecol = (lane & 3) * 2;
#pragma unroll
    for (int mt = 0; mt < 4; ++mt) {
#pragma unroll
        for (int nt = 0; nt < 4; ++nt) {
#pragma unroll
            for (int half = 0; half < 2; ++half) {
                const int row = m0 + wm + mt * 16 + erow + half * 8;
                const int col = n0 + wn + nt * 8 + ecol;
                float v0 = acc[mt][nt][half * 2 + 0] + bias[col];
                float v1 = acc[mt][nt][half * 2 + 1] + bias[col + 1];
                if (mode == 0) {
                    const int bb = row >> 11, s = row & 2047;
                    const int part = col >> 10;
                    const int dd = col & 1023;
                    const int h = dd >> 6, hd = dd & 63;
                    const int bh = (bb << 4) + h;
                    if (part == 0) { v0 *= 0.125f; v1 *= 0.125f; }
                    __nv_bfloat16 h0, l0, h1, l1;
                    split2(v0, h0, l0); split2(v1, h1, l1);
                    if (part == 2) {
                        const size_t base = ((size_t)bh * DHEAD + hd) * SEQ + s;
                        s_vt_hi[base] = h0;       s_vt_lo[base] = l0;
                        s_vt_hi[base + SEQ] = h1; s_vt_lo[base + SEQ] = l1;
                    } else {
                        const size_t base = ((size_t)bh * SEQ + s) * DHEAD + hd;
                        __nv_bfloat16* dh_ = (part == 0) ? s_q_hi : s_k_hi;
                        __nv_bfloat16* dl_ = (part == 0) ? s_q_lo : s_k_lo;
                        *(uint32_t*)(dh_ + base) = packbf(h0, h1);
                        *(uint32_t*)(dl_ + base) = packbf(l0, l1);
                    }
                } else {
                    *(float2*)(outp + (size_t)row * DIM + col) = make_float2(v0, v1);
                }
            }
        }
    }
}

// ---------------------------------------------------------------------------
// Tensor-core flash attention (bf16 split-2, fp32 softmax).
// CTA: 128 query rows x one (b,h); 4 warps, 32 rows each; KV tiles of 64.
// Output written as bf16 hi/lo splits straight into the proj GEMM A operand.
// ---------------------------------------------------------------------------
#define AROWB 144                     // 128B data + 16B pad
#define ASM_QH 0
#define ASM_QL (128 * AROWB)
#define ASM_KH (2 * 128 * AROWB)
#define ASM_KL (ASM_KH + 64 * AROWB)
#define ASM_VH (ASM_KL + 64 * AROWB)
#define ASM_VL (ASM_VH + 64 * AROWB)
#define ASM_BYTES (ASM_VL + 64 * AROWB)   // 73728

__global__ __launch_bounds__(128) void attn_tc_kernel()
{
    extern __shared__ char asmem[];
    const uint32_t sb = smem_u32(asmem);
    const int tid  = threadIdx.x;
    const int w    = tid >> 5;
    const int lane = tid & 31;
    const int qt   = blockIdx.x;         // 0..15
    const int bh   = blockIdx.y;         // 0..31
    const int q0   = qt * 128;

    const __nv_bfloat16* Qh = s_q_hi + (size_t)bh * SEQ * DHEAD;
    const __nv_bfloat16* Ql = s_q_lo + (size_t)bh * SEQ * DHEAD;
    const __nv_bfloat16* Kh = s_k_hi + (size_t)bh * SEQ * DHEAD;
    const __nv_bfloat16* Kl = s_k_lo + (size_t)bh * SEQ * DHEAD;
    const __nv_bfloat16* Vh = s_vt_hi + (size_t)bh * DHEAD * SEQ;
    const __nv_bfloat16* Vl = s_vt_lo + (size_t)bh * DHEAD * SEQ;

    // load Q tile (128 rows x 64 bf16) hi/lo
#pragma unroll
    for (int i = 0; i < 8; ++i) {
        const int c = tid + i * 128;          // 0..1023
        const int row = c >> 3, seg = c & 7;
        const uint32_t so = row * AROWB + seg * 16;
        const size_t go = (size_t)(q0 + row) * DHEAD + seg * 8;
        *(uint4*)(asmem + ASM_QH + so) = *(const uint4*)(Qh + go);
        *(uint4*)(asmem + ASM_QL + so) = *(const uint4*)(Ql + go);
    }

    // fragment addressing
    const int ar = lane & 15, ahh = lane >> 4;
    const int grp = lane >> 3, l8 = lane & 7;
    const int row0 = lane >> 2, coll = (lane & 3) * 2;

    float m_run[4], l_run[4];
#pragma unroll
    for (int i = 0; i < 4; ++i) { m_run[i] = -1e30f; l_run[i] = 0.f; }
    float oacc[2][8][4];
#pragma unroll
    for (int mt = 0; mt < 2; ++mt)
#pragma unroll
        for (int nt = 0; nt < 8; ++nt)
#pragma unroll
            for (int e = 0; e < 4; ++e) oacc[mt][nt][e] = 0.f;

    const int ntiles = qt * 2 + 2;
    for (int kt = 0; kt < ntiles; ++kt) {
        const int kv0 = kt * 64;
        __syncthreads();
        // load K (k-major [key,dh]) and VT (k-major [dh,key]) tiles hi/lo
#pragma unroll
        for (int i = 0; i < 4; ++i) {
            const int c = tid + i * 128;      // 0..511
            const int row = c >> 3, seg = c & 7;
            const uint32_t so = row * AROWB + seg * 16;
            const size_t gk = (size_t)(kv0 + row) * DHEAD + seg * 8;
            const size_t gv = (size_t)row * SEQ + kv0 + seg * 8;
            *(uint4*)(asmem + ASM_KH + so) = *(const uint4*)(Kh + gk);
            *(uint4*)(asmem + ASM_KL + so) = *(const uint4*)(Kl + gk);
            *(uint4*)(asmem + ASM_VH + so) = *(const uint4*)(Vh + gv);
            *(uint4*)(asmem + ASM_VL + so) = *(const uint4*)(Vl + gv);
        }
        __syncthreads();

        // ---- scores: S = Q K^T (split-2) ----
        float s[2][8][4];
#pragma unroll
        for (int mt = 0; mt < 2; ++mt)
#pragma unroll
            for (int nt = 0; nt < 8; ++nt)
#pragma unroll
                for (int e = 0; e < 4; ++e) s[mt][nt][e] = 0.f;

#pragma unroll
        for (int ks = 0; ks < 4; ++ks) {
            uint32_t kbh[4][4], kbl[4][4];
#pragma unroll
            for (int nb = 0; nb < 4; ++nb) {
                const uint32_t bo = (uint32_t)(((grp >> 1) * 8 + l8 + nb * 16) * AROWB +
                                               (grp & 1) * 16 + ks * 32);
                ldsm4(sb + ASM_KH + bo, kbh[nb][0], kbh[nb][1], kbh[nb][2], kbh[nb][3]);
                ldsm4(sb + ASM_KL + bo, kbl[nb][0], kbl[nb][1], kbl[nb][2], kbl[nb][3]);
            }
#pragma unroll
            for (int mt = 0; mt < 2; ++mt) {
                const uint32_t ao = (uint32_t)((w * 32 + mt * 16 + ar) * AROWB +
                                               ahh * 16 + ks * 32);
                uint32_t qh0, qh1, qh2, qh3, ql0, ql1, ql2, ql3;
                ldsm4(sb + ASM_QH + ao, qh0, qh1, qh2, qh3);
                ldsm4(sb + ASM_QL + ao, ql0, ql1, ql2, ql3);
#pragma unroll
                for (int nt = 0; nt < 8; ++nt) {
                    float* c = s[mt][nt];
                    const int nb = nt >> 1, p = nt & 1;
                    mma_bf16(c[0], c[1], c[2], c[3], qh0, qh1, qh2, qh3,
                             kbh[nb][p * 2], kbh[nb][p * 2 + 1]);
                    mma_bf16(c[0], c[1], c[2], c[3], qh0, qh1, qh2, qh3,
                             kbl[nb][p * 2], kbl[nb][p * 2 + 1]);
                    mma_bf16(c[0], c[1], c[2], c[3], ql0, ql1, ql2, ql3,
                             kbh[nb][p * 2], kbh[nb][p * 2 + 1]);
                }
            }
        }

        // ---- causal mask (only the last two tiles can cross the diagonal) ----
        if (kt >= qt * 2) {
#pragma unroll
            for (int mt = 0; mt < 2; ++mt) {
                const int rbase = q0 + w * 32 + mt * 16 + row0;
#pragma unroll
                for (int nt = 0; nt < 8; ++nt) {
                    const int cb = kv0 + nt * 8 + coll;
                    if (cb > rbase)     s[mt][nt][0] = -10000.f;
                    if (cb + 1 > rbase) s[mt][nt][1] = -10000.f;
                    if (cb > rbase + 8)     s[mt][nt][2] = -10000.f;
                    if (cb + 1 > rbase + 8) s[mt][nt][3] = -10000.f;
                }
            }
        }

        // ---- online softmax ----
        float corr[4];
#pragma unroll
        for (int slot = 0; slot < 4; ++slot) {
            const int mt = slot >> 1, h2 = slot & 1;
            float tm = -1e30f;
#pragma unroll
            for (int nt = 0; nt < 8; ++nt)
                tm = fmaxf(tm, fmaxf(s[mt][nt][h2 * 2], s[mt][nt][h2 * 2 + 1]));
            tm = fmaxf(tm, __shfl_xor_sync(0xffffffffu, tm, 1));
            tm = fmaxf(tm, __shfl_xor_sync(0xffffffffu, tm, 2));
            const float mnew = fmaxf(m_run[slot], tm);
            corr[slot] = __expf(m_run[slot] - mnew);
            m_run[slot] = mnew;
            l_run[slot] *= corr[slot];
        }
#pragma unroll
        for (int mt = 0; mt < 2; ++mt)
#pragma unroll
            for (int nt = 0; nt < 8; ++nt) {
                oacc[mt][nt][0] *= corr[mt * 2];
                oacc[mt][nt][1] *= corr[mt * 2];
                oacc[mt][nt][2] *= corr[mt * 2 + 1];
                oacc[mt][nt][3] *= corr[mt * 2 + 1];
            }

        // ---- P = exp(S - m), split-2 pack into A fragments ----
        uint32_t ph[2][8][2], pl[2][8][2];
#pragma unroll
        for (int mt = 0; mt < 2; ++mt)
#pragma unroll
            for (int nt = 0; nt < 8; ++nt) {
                const float p0 = __expf(s[mt][nt][0] - m_run[mt * 2]);
                const float p1 = __expf(s[mt][nt][1] - m_run[mt * 2]);
                const float p2 = __expf(s[mt][nt][2] - m_run[mt * 2 + 1]);
                const float p3 = __expf(s[mt][nt][3] - m_run[mt * 2 + 1]);
                l_run[mt * 2]     += p0 + p1;
                l_run[mt * 2 + 1] += p2 + p3;
                __nv_bfloat16 h0, lo0, h1, lo1, h2, lo2, h3, lo3;
                split2(p0, h0, lo0); split2(p1, h1, lo1);
                split2(p2, h2, lo2); split2(p3, h3, lo3);
                ph[mt][nt][0] = packbf(h0, h1);  ph[mt][nt][1] = packbf(h2, h3);
                pl[mt][nt][0] = packbf(lo0, lo1); pl[mt][nt][1] = packbf(lo2, lo3);
            }

        // ---- O += P V  (split-2; B = V^T fragments, n = dh, k = key) ----
#pragma unroll
        for (int ks = 0; ks < 4; ++ks) {
            uint32_t vbh[4][4], vbl[4][4];
#pragma unroll
            for (int nb = 0; nb < 4; ++nb) {
                const uint32_t bo = (uint32_t)(((grp >> 1) * 8 + l8 + nb * 16) * AROWB +
                                               (grp & 1) * 16 + ks * 32);
                ldsm4(sb + ASM_VH + bo, vbh[nb][0], vbh[nb][1], vbh[nb][2], vbh[nb][3]);
                ldsm4(sb + ASM_VL + bo, vbl[nb][0], vbl[nb][1], vbl[nb][2], vbl[nb][3]);
            }
#pragma unroll
            for (int mt = 0; mt < 2; ++mt) {
                const uint32_t a0h = ph[mt][ks * 2][0],     a1h = ph[mt][ks * 2][1];
                const uint32_t a2h = ph[mt][ks * 2 + 1][0], a3h = ph[mt][ks * 2 + 1][1];
                const uint32_t a0l = pl[mt][ks * 2][0],     a1l = pl[mt][ks * 2][1];
                const uint32_t a2l = pl[mt][ks * 2 + 1][0], a3l = pl[mt][ks * 2 + 1][1];
#pragma unroll
                for (int nt = 0; nt < 8; ++nt) {
                    float* c = oacc[mt][nt];
                    const int nb = nt >> 1, p = nt & 1;
                    mma_bf16(c[0], c[1], c[2], c[3], a0h, a1h, a2h, a3h,
                             vbh[nb][p * 2], vbh[nb][p * 2 + 1]);
                    mma_bf16(c[0], c[1], c[2], c[3], a0h, a1h, a2h, a3h,
                             vbl[nb][p * 2], vbl[nb][p * 2 + 1]);
                    mma_bf16(c[0], c[1], c[2], c[3], a0l, a1l, a2l, a3l,
                             vbh[nb][p * 2], vbh[nb][p * 2 + 1]);
                }
            }
        }
    }

    // ---- finalize: divide by row sums, split-2, write proj A operand ----
    float inv[4];
#pragma unroll
    for (int slot = 0; slot < 4; ++slot) {
        float lt = l_run[slot];
        lt += __shfl_xor_sync(0xffffffffu, lt, 1);
        lt += __shfl_xor_sync(0xffffffffu, lt, 2);
        inv[slot] = 1.f / lt;
    }
    const int b = bh >> 4, h = bh & 15;
#pragma unroll
    for (int mt = 0; mt < 2; ++mt) {
#pragma unroll
        for (int half = 0; half < 2; ++half) {
            const size_t orow = (size_t)b * SEQ + q0 + w * 32 + mt * 16 + row0 + half * 8;
            const float iv = inv[mt * 2 + half];
#pragma unroll
            for (int nt = 0; nt < 8; ++nt) {
                const int col = h * DHEAD + nt * 8 + coll;
                const float v0 = oacc[mt][nt][half * 2 + 0] * iv;
                const float v1 = oacc[mt][nt][half * 2 + 1] * iv;
                __nv_bfloat16 h0, l0, h1, l1;
                split2(v0, h0, l0); split2(v1, h1, l1);
                *(uint32_t*)(s_a_hi + orow * DIM + col) = packbf(h0, h1);
                *(uint32_t*)(s_a_lo + orow * DIM + col) = packbf(l0, l1);
            }
        }
    }
}

// ---------------------------------------------------------------------------
extern "C" void kernel_launch(void* const* d_in, const int* in_sizes, int n_in,
                              void* d_out, int out_size)
{
    const float* x      = (const float*)d_in[0];
    const float* w_attn = (const float*)d_in[1];
    const float* b_attn = (const float*)d_in[2];
    const float* w_proj = (const float*)d_in[3];
    const float* b_proj = (const float*)d_in[4];
    float* out = (float*)d_out;

    __nv_bfloat16 *xa_hi, *xa_lo, *wq_hi, *wq_lo, *wp_hi, *wp_lo;
    cudaGetSymbolAddress((void**)&xa_hi, s_a_hi);
    cudaGetSymbolAddress((void**)&xa_lo, s_a_lo);
    cudaGetSymbolAddress((void**)&wq_hi, s_wq_hi);
    cudaGetSymbolAddress((void**)&wq_lo, s_wq_lo);
    cudaGetSymbolAddress((void**)&wp_hi, s_wp_hi);
    cudaGetSymbolAddress((void**)&wp_lo, s_wp_lo);

    cudaFuncSetAttribute(attn_tc_kernel,
                         cudaFuncAttributeMaxDynamicSharedMemorySize, ASM_BYTES);

    // 1) split x -> bf16 hi/lo (A operand of QKV GEMM)
    split_kernel<<<(MROWS * KTOT / 4 + 255) / 256, 256>>>(x, xa_hi, xa_lo, MROWS * KTOT / 4);
    // 2) transpose+split weights
    transp_split_kernel<<<dim3(NQKV / 32, KTOT / 32), dim3(32, 8)>>>(w_attn, KTOT, NQKV, wq_hi, wq_lo);
    transp_split_kernel<<<dim3(DIM / 32, KTOT / 32), dim3(32, 8)>>>(w_proj, KTOT, DIM, wp_hi, wp_lo);
    // 3) QKV GEMM -> bf16 split q/k/vt
    tc_gemm_kernel<<<dim3(NQKV / BN, MROWS / BM), 256>>>(
        xa_hi, xa_lo, wq_hi, wq_lo, b_attn, nullptr, 0);
    // 4) tensor-core flash attention -> writes s_a_hi/s_a_lo
    attn_tc_kernel<<<dim3(SEQ / 128, BATCH * NHEAD), 128, ASM_BYTES>>>();
    // 5) output projection
    tc_gemm_kernel<<<dim3(DIM / BN, MROWS / BM), 256>>>(
        xa_hi, xa_lo, wp_hi, wp_lo, b_proj, out, 1);
}